// round 6
// baseline (speedup 1.0000x reference)
#include <cuda_runtime.h>
#include <math.h>
#include <stdint.h>

// Problem constants
#define BB 4
#define NN 8192
#define KK 16
#define BNK (BB * NN * KK)   // 524288

// ---------------------------------------------------------------------------
// Device scratch (no allocations allowed)
// ---------------------------------------------------------------------------
__device__ float  g_S[BNK];            // softmax(logits)
__device__ double g_StS[BB * KK * KK]; // per-batch S^T S
__device__ double g_num;               // sum W[n,m] * dot(S_n, S_m)
__device__ double g_den;               // sum W

// ---------------------------------------------------------------------------
// Packed f32x2 helpers (FFMA2 path — ptxas won't emit these from plain C++)
// ---------------------------------------------------------------------------
typedef unsigned long long u64p; // carrier for packed 2 x fp32

__device__ __forceinline__ u64p pk2(float lo, float hi) {
    u64p d;
    asm("mov.b64 %0, {%1, %2};" : "=l"(d) : "f"(lo), "f"(hi));
    return d;
}
__device__ __forceinline__ u64p mul2(u64p a, u64p b) {
    u64p d;
    asm("mul.rn.f32x2 %0, %1, %2;" : "=l"(d) : "l"(a), "l"(b));
    return d;
}
__device__ __forceinline__ u64p fma2(u64p a, u64p b, u64p c) {
    u64p d;
    asm("fma.rn.f32x2 %0, %1, %2, %3;" : "=l"(d) : "l"(a), "l"(b), "l"(c));
    return d;
}
__device__ __forceinline__ float hsum2(u64p d) {
    float lo, hi;
    asm("mov.b64 {%0, %1}, %2;" : "=f"(lo), "=f"(hi) : "l"(d));
    return lo + hi;
}

// ---------------------------------------------------------------------------
// Zero the scalar/StS accumulators (fresh each call — deterministic)
// ---------------------------------------------------------------------------
__global__ void zero_kernel() {
    int t = threadIdx.x;
    if (t < BB * KK * KK) g_StS[t] = 0.0;
    if (t == 0) { g_num = 0.0; g_den = 0.0; }
}

// ---------------------------------------------------------------------------
// Softmax over K=16 per row. One thread per row. Writes g_S and (optionally)
// the S region of d_out.
// ---------------------------------------------------------------------------
__global__ void softmax_kernel(const float* __restrict__ logits,
                               float* __restrict__ outS) {
    int row = blockIdx.x * blockDim.x + threadIdx.x; // 0 .. B*N-1
    const float4* lp = (const float4*)(logits + (size_t)row * KK);
    float4 v0 = lp[0], v1 = lp[1], v2 = lp[2], v3 = lp[3];
    float v[16] = { v0.x, v0.y, v0.z, v0.w, v1.x, v1.y, v1.z, v1.w,
                    v2.x, v2.y, v2.z, v2.w, v3.x, v3.y, v3.z, v3.w };
    float mx = v[0];
#pragma unroll
    for (int i = 1; i < 16; i++) mx = fmaxf(mx, v[i]);
    float s = 0.f;
#pragma unroll
    for (int i = 0; i < 16; i++) { v[i] = expf(v[i] - mx); s += v[i]; }
    float inv = 1.0f / s;
    float4 o0, o1, o2, o3;
    o0 = make_float4(v[0] * inv, v[1] * inv, v[2] * inv, v[3] * inv);
    o1 = make_float4(v[4] * inv, v[5] * inv, v[6] * inv, v[7] * inv);
    o2 = make_float4(v[8] * inv, v[9] * inv, v[10] * inv, v[11] * inv);
    o3 = make_float4(v[12] * inv, v[13] * inv, v[14] * inv, v[15] * inv);
    float4* sp = (float4*)(g_S + (size_t)row * KK);
    sp[0] = o0; sp[1] = o1; sp[2] = o2; sp[3] = o3;
    if (outS) {
        float4* op = (float4*)(outS + (size_t)row * KK);
        op[0] = o0; op[1] = o1; op[2] = o2; op[3] = o3;
    }
}

// ---------------------------------------------------------------------------
// StS[b,k,j] = sum_n S[b,n,k] * S[b,n,j].
// Grid (B, 16): each block handles 512 rows of one batch.
// 256 threads <-> the 16x16 (k,j) pairs. fp32 per 128-row chunk, double total.
// ---------------------------------------------------------------------------
__global__ void sts_kernel() {
    int b = blockIdx.x;
    int part = blockIdx.y;
    int t = threadIdx.x;
    int k = t >> 4, j = t & 15;
    __shared__ float sh[128 * 16];
    double tot = 0.0;
    int nbeg = part * 512, nend = nbeg + 512;
    for (int n0 = nbeg; n0 < nend; n0 += 128) {
        const float4* src = (const float4*)(g_S + ((size_t)b * NN + n0) * KK);
        float4* dst = (float4*)sh;
        dst[t]       = src[t];
        dst[t + 256] = src[t + 256];
        __syncthreads();
        float acc = 0.f;
#pragma unroll 8
        for (int r = 0; r < 128; r++)
            acc = fmaf(sh[r * 16 + k], sh[r * 16 + j], acc);
        tot += (double)acc;
        __syncthreads();
    }
    atomicAdd(&g_StS[b * 256 + t], tot);
}

// ---------------------------------------------------------------------------
// Main streaming pass over W:
//   num += W[b,n,m] * dot16(S[b,n,:], S[b,m,:]);  den += W[b,n,m]
// Block: 256 threads = 8 warps. Each warp: 32 lanes x 4 consecutive columns m
// (S_m packed into 64 regs), walks 128 rows n with coalesced LDG.128 of W.
// Grid: (N/128 col strips, N/1024 row groups, B).
// ---------------------------------------------------------------------------
__global__ void __launch_bounds__(256, 2)
w_pass_kernel(const float* __restrict__ W) {
    const int lane = threadIdx.x & 31;
    const int warp = threadIdx.x >> 5;
    const int b  = blockIdx.z;
    const int c0 = blockIdx.x * 128 + lane * 4;     // first of 4 columns m
    const int r0 = blockIdx.y * 1024 + warp * 128;  // first of 128 rows n

    // Pre-pack S_m for this thread's 4 columns: 4 x 8 packed pairs
    u64p sm[4][8];
#pragma unroll
    for (int jj = 0; jj < 4; jj++) {
        const float4* sp = (const float4*)(g_S + ((size_t)b * NN + (c0 + jj)) * KK);
        float4 a = __ldg(sp), b4 = __ldg(sp + 1), c = __ldg(sp + 2), d = __ldg(sp + 3);
        sm[jj][0] = pk2(a.x, a.y);  sm[jj][1] = pk2(a.z, a.w);
        sm[jj][2] = pk2(b4.x, b4.y); sm[jj][3] = pk2(b4.z, b4.w);
        sm[jj][4] = pk2(c.x, c.y);  sm[jj][5] = pk2(c.z, c.w);
        sm[jj][6] = pk2(d.x, d.y);  sm[jj][7] = pk2(d.z, d.w);
    }

    const float* Wp = W + ((size_t)b * NN + r0) * NN + c0;
    const float* Sp = g_S + ((size_t)b * NN + r0) * KK;

    u64p acc0 = 0, acc1 = 0, acc2 = 0, acc3 = 0; // packed num accumulators
    float den0 = 0.f, den1 = 0.f;

#pragma unroll 2
    for (int i = 0; i < 128; i++) {
        float4 w = __ldg((const float4*)Wp);
        // warp-uniform broadcast load of S_n (L1-hit after first touch)
        float4 a  = __ldg((const float4*)(Sp));
        float4 b4 = __ldg((const float4*)(Sp + 4));
        float4 c  = __ldg((const float4*)(Sp + 8));
        float4 d  = __ldg((const float4*)(Sp + 12));
        u64p sn[8];
        sn[0] = pk2(a.x, a.y);  sn[1] = pk2(a.z, a.w);
        sn[2] = pk2(b4.x, b4.y); sn[3] = pk2(b4.z, b4.w);
        sn[4] = pk2(c.x, c.y);  sn[5] = pk2(c.z, c.w);
        sn[6] = pk2(d.x, d.y);  sn[7] = pk2(d.z, d.w);

        // 4 independent packed dot chains (ILP = 4)
        u64p d0 = mul2(sm[0][0], sn[0]);
        u64p d1 = mul2(sm[1][0], sn[0]);
        u64p d2 = mul2(sm[2][0], sn[0]);
        u64p d3 = mul2(sm[3][0], sn[0]);
#pragma unroll
        for (int kk = 1; kk < 8; kk++) {
            d0 = fma2(sm[0][kk], sn[kk], d0);
            d1 = fma2(sm[1][kk], sn[kk], d1);
            d2 = fma2(sm[2][kk], sn[kk], d2);
            d3 = fma2(sm[3][kk], sn[kk], d3);
        }
        // num += w_j * (d_j.lo + d_j.hi), deferred: accumulate packed, hsum once
        acc0 = fma2(pk2(w.x, w.x), d0, acc0);
        acc1 = fma2(pk2(w.y, w.y), d1, acc1);
        acc2 = fma2(pk2(w.z, w.z), d2, acc2);
        acc3 = fma2(pk2(w.w, w.w), d3, acc3);
        den0 += w.x + w.y;
        den1 += w.z + w.w;

        Wp += NN;
        Sp += KK;
    }

    float tnum = (hsum2(acc0) + hsum2(acc1)) + (hsum2(acc2) + hsum2(acc3));
    float tden = den0 + den1;

    // Block reduction -> one double atomic per block
    __shared__ float rn[256], rd[256];
    int t = threadIdx.x;
    rn[t] = tnum; rd[t] = tden;
    __syncthreads();
#pragma unroll
    for (int s = 128; s > 0; s >>= 1) {
        if (t < s) { rn[t] += rn[t + s]; rd[t] += rd[t + s]; }
        __syncthreads();
    }
    if (t == 0) {
        atomicAdd(&g_num, (double)rn[0]);
        atomicAdd(&g_den, (double)rd[0]);
    }
}

// ---------------------------------------------------------------------------
// Finalize: loss = -(num/den) + sqrt(sum_b ||StS_b - I||_F^2) / B
// ---------------------------------------------------------------------------
__global__ void finalize_kernel(float* __restrict__ out, int loss_idx) {
    int t = threadIdx.x; // 0..255 == (k,j) pair
    int k = t >> 4, j = t & 15;
    float s = 0.f;
#pragma unroll
    for (int b = 0; b < BB; b++) {
        float v = (float)g_StS[b * 256 + t];
        float diff = v - (k == j ? 1.0f : 0.0f);
        s += diff * diff;
    }
    __shared__ float red[256];
    red[t] = s;
    __syncthreads();
#pragma unroll
    for (int st = 128; st > 0; st >>= 1) {
        if (t < st) red[t] += red[t + st];
        __syncthreads();
    }
    if (t == 0) {
        float ortho = sqrtf(red[0]) / (float)BB;
        float cut_loss = (float)(g_num / g_den);
        out[loss_idx] = -cut_loss + ortho;
    }
}

// ---------------------------------------------------------------------------
// Launch
// ---------------------------------------------------------------------------
extern "C" void kernel_launch(void* const* d_in, const int* in_sizes, int n_in,
                              void* d_out, int out_size) {
    const float* W = nullptr;
    const float* logits = nullptr;
    for (int i = 0; i < n_in; i++) {
        long sz = (long)in_sizes[i];
        if (sz == (long)BB * NN * NN)      W      = (const float*)d_in[i];
        else if (sz == (long)BB * NN * KK) logits = (const float*)d_in[i];
        // features [B,N,D] is unused by the reference computation
    }
    float* out = (float*)d_out;

    bool want_S    = (out_size >= BNK);
    bool want_loss = (out_size == 1) || (out_size == BNK + 1);

    zero_kernel<<<1, 1024>>>();
    softmax_kernel<<<(BB * NN) / 256, 256>>>(logits, want_S ? out : nullptr);
    if (want_loss) {
        sts_kernel<<<dim3(BB, 16), 256>>>();
        w_pass_kernel<<<dim3(NN / 128, NN / 1024, BB), 256>>>(W);
        finalize_kernel<<<1, 256>>>(out, (out_size == 1) ? 0 : BNK);
    }
}

// round 7
// speedup vs baseline: 1.4819x; 1.4819x over previous
#include <cuda_runtime.h>
#include <math.h>
#include <stdint.h>

// Problem constants
#define BB 4
#define NN 8192
#define KK 16
#define BNK (BB * NN * KK)   // 524288

// ---------------------------------------------------------------------------
// Device scratch (no allocations allowed)
// ---------------------------------------------------------------------------
__device__ float  g_S[BNK];            // softmax(logits)
__device__ double g_StS[BB * KK * KK]; // per-batch S^T S
__device__ double g_num;               // sum W[n,m] * dot(S_n, S_m)
__device__ double g_den;               // sum W

// ---------------------------------------------------------------------------
// Packed f32x2 helpers (FFMA2 path — ptxas won't emit these from plain C++)
// ---------------------------------------------------------------------------
typedef unsigned long long u64p; // carrier for packed 2 x fp32

__device__ __forceinline__ u64p pk2(float lo, float hi) {
    u64p d;
    asm("mov.b64 %0, {%1, %2};" : "=l"(d) : "f"(lo), "f"(hi));
    return d;
}
__device__ __forceinline__ u64p mul2(u64p a, u64p b) {
    u64p d;
    asm("mul.rn.f32x2 %0, %1, %2;" : "=l"(d) : "l"(a), "l"(b));
    return d;
}
__device__ __forceinline__ u64p fma2(u64p a, u64p b, u64p c) {
    u64p d;
    asm("fma.rn.f32x2 %0, %1, %2, %3;" : "=l"(d) : "l"(a), "l"(b), "l"(c));
    return d;
}
__device__ __forceinline__ u64p add2(u64p a, u64p b) {
    u64p d;
    asm("add.rn.f32x2 %0, %1, %2;" : "=l"(d) : "l"(a), "l"(b));
    return d;
}
__device__ __forceinline__ float hsum2(u64p d) {
    float lo, hi;
    asm("mov.b64 {%0, %1}, %2;" : "=f"(lo), "=f"(hi) : "l"(d));
    return lo + hi;
}

// ---------------------------------------------------------------------------
// Zero the scalar/StS accumulators (fresh each call — deterministic)
// ---------------------------------------------------------------------------
__global__ void zero_kernel() {
    int t = threadIdx.x;
    if (t < BB * KK * KK) g_StS[t] = 0.0;
    if (t == 0) { g_num = 0.0; g_den = 0.0; }
}

// ---------------------------------------------------------------------------
// Softmax over K=16 per row. One thread per row.
// ---------------------------------------------------------------------------
__global__ void softmax_kernel(const float* __restrict__ logits,
                               float* __restrict__ outS) {
    int row = blockIdx.x * blockDim.x + threadIdx.x; // 0 .. B*N-1
    const float4* lp = (const float4*)(logits + (size_t)row * KK);
    float4 v0 = lp[0], v1 = lp[1], v2 = lp[2], v3 = lp[3];
    float v[16] = { v0.x, v0.y, v0.z, v0.w, v1.x, v1.y, v1.z, v1.w,
                    v2.x, v2.y, v2.z, v2.w, v3.x, v3.y, v3.z, v3.w };
    float mx = v[0];
#pragma unroll
    for (int i = 1; i < 16; i++) mx = fmaxf(mx, v[i]);
    float s = 0.f;
#pragma unroll
    for (int i = 0; i < 16; i++) { v[i] = expf(v[i] - mx); s += v[i]; }
    float inv = 1.0f / s;
    float4 o0 = make_float4(v[0]*inv,  v[1]*inv,  v[2]*inv,  v[3]*inv);
    float4 o1 = make_float4(v[4]*inv,  v[5]*inv,  v[6]*inv,  v[7]*inv);
    float4 o2 = make_float4(v[8]*inv,  v[9]*inv,  v[10]*inv, v[11]*inv);
    float4 o3 = make_float4(v[12]*inv, v[13]*inv, v[14]*inv, v[15]*inv);
    float4* sp = (float4*)(g_S + (size_t)row * KK);
    sp[0] = o0; sp[1] = o1; sp[2] = o2; sp[3] = o3;
    if (outS) {
        float4* op = (float4*)(outS + (size_t)row * KK);
        op[0] = o0; op[1] = o1; op[2] = o2; op[3] = o3;
    }
}

// ---------------------------------------------------------------------------
// StS[b,k,j] = sum_n S[b,n,k] * S[b,n,j].
// ---------------------------------------------------------------------------
__global__ void sts_kernel() {
    int b = blockIdx.x;
    int part = blockIdx.y;
    int t = threadIdx.x;
    int k = t >> 4, j = t & 15;
    __shared__ float sh[128 * 16];
    double tot = 0.0;
    int nbeg = part * 512, nend = nbeg + 512;
    for (int n0 = nbeg; n0 < nend; n0 += 128) {
        const float4* src = (const float4*)(g_S + ((size_t)b * NN + n0) * KK);
        float4* dst = (float4*)sh;
        dst[t]       = src[t];
        dst[t + 256] = src[t + 256];
        __syncthreads();
        float acc = 0.f;
#pragma unroll 8
        for (int r = 0; r < 128; r++)
            acc = fmaf(sh[r * 16 + k], sh[r * 16 + j], acc);
        tot += (double)acc;
        __syncthreads();
    }
    atomicAdd(&g_StS[b * 256 + t], tot);
}

// ---------------------------------------------------------------------------
// Main streaming pass over W:
//   num += W[b,n,m] * dot16(S[b,n,:], S[b,m,:]);  den += W[b,n,m]
//
// Block: 256 threads = 8 warps. Each thread owns 4 consecutive columns m
// (S_m pre-packed in 64 regs). ALL warps of a block share the same rows n:
// S_n rows are staged in an 8KB shared tile (broadcast LDS, no L1/L2 reload,
// shared across the 8 warps). Inner loop front-batches W for 4 rows
// (4 independent LDG.128 -> MLP=4 per warp) before computing them.
// Grid: (N/1024 col strips, N/256 row groups, B) = (8, 32, 4) = 1024 blocks.
// ---------------------------------------------------------------------------
__global__ void __launch_bounds__(256, 2)
w_pass_kernel(const float* __restrict__ W) {
    __shared__ float sh[128 * 16];      // one 128-row S tile, 8KB
    const int lane = threadIdx.x & 31;
    const int warp = threadIdx.x >> 5;
    const int b  = blockIdx.z;
    const int c0 = (blockIdx.x * 8 + warp) * 128 + lane * 4; // 4 columns m
    const int r0 = blockIdx.y * 256;                          // 256 rows, 2 tiles

    // Pre-pack S_m for this thread's 4 columns: 4 x 8 packed pairs (64 regs)
    u64p sm[4][8];
#pragma unroll
    for (int jj = 0; jj < 4; jj++) {
        const float4* sp = (const float4*)(g_S + ((size_t)b * NN + (c0 + jj)) * KK);
        float4 a = __ldg(sp), b4 = __ldg(sp + 1), c = __ldg(sp + 2), d = __ldg(sp + 3);
        sm[jj][0] = pk2(a.x, a.y);   sm[jj][1] = pk2(a.z, a.w);
        sm[jj][2] = pk2(b4.x, b4.y); sm[jj][3] = pk2(b4.z, b4.w);
        sm[jj][4] = pk2(c.x, c.y);   sm[jj][5] = pk2(c.z, c.w);
        sm[jj][6] = pk2(d.x, d.y);   sm[jj][7] = pk2(d.z, d.w);
    }

    u64p acc0 = 0, acc1 = 0, acc2 = 0, acc3 = 0; // packed num accumulators
    u64p den0 = 0, den1 = 0;                     // packed den accumulators

#pragma unroll 1
    for (int tile = 0; tile < 2; tile++) {
        const int rbase = r0 + tile * 128;
        __syncthreads(); // protect sh from previous tile's readers
        {
            const float4* src = (const float4*)(g_S + ((size_t)b * NN + rbase) * KK);
            float4* dst = (float4*)sh;
            dst[threadIdx.x]       = src[threadIdx.x];
            dst[threadIdx.x + 256] = src[threadIdx.x + 256];
        }
        __syncthreads();

        const float* Wp = W + ((size_t)b * NN + rbase) * NN + c0;

#pragma unroll 1
        for (int r = 0; r < 128; r += 4) {
            // Front-batched independent W loads: MLP = 4 per warp
            float4 w0 = __ldg((const float4*)(Wp));
            float4 w1 = __ldg((const float4*)(Wp + (size_t)NN));
            float4 w2 = __ldg((const float4*)(Wp + 2 * (size_t)NN));
            float4 w3 = __ldg((const float4*)(Wp + 3 * (size_t)NN));
            Wp += 4 * (size_t)NN;

#pragma unroll
            for (int j = 0; j < 4; j++) {
                float4 w = (j == 0) ? w0 : (j == 1) ? w1 : (j == 2) ? w2 : w3;
                const float4* sp = (const float4*)(sh + (size_t)(r + j) * KK);
                float4 a = sp[0], e = sp[1], c = sp[2], d = sp[3]; // broadcast LDS
                u64p sn0 = pk2(a.x, a.y), sn1 = pk2(a.z, a.w);
                u64p sn2 = pk2(e.x, e.y), sn3 = pk2(e.z, e.w);
                u64p sn4 = pk2(c.x, c.y), sn5 = pk2(c.z, c.w);
                u64p sn6 = pk2(d.x, d.y), sn7 = pk2(d.z, d.w);

                // 4 independent packed dot chains (ILP = 4)
                u64p d0 = mul2(sm[0][0], sn0);
                u64p d1 = mul2(sm[1][0], sn0);
                u64p d2 = mul2(sm[2][0], sn0);
                u64p d3 = mul2(sm[3][0], sn0);
                d0 = fma2(sm[0][1], sn1, d0); d1 = fma2(sm[1][1], sn1, d1);
                d2 = fma2(sm[2][1], sn1, d2); d3 = fma2(sm[3][1], sn1, d3);
                d0 = fma2(sm[0][2], sn2, d0); d1 = fma2(sm[1][2], sn2, d1);
                d2 = fma2(sm[2][2], sn2, d2); d3 = fma2(sm[3][2], sn2, d3);
                d0 = fma2(sm[0][3], sn3, d0); d1 = fma2(sm[1][3], sn3, d1);
                d2 = fma2(sm[2][3], sn3, d2); d3 = fma2(sm[3][3], sn3, d3);
                d0 = fma2(sm[0][4], sn4, d0); d1 = fma2(sm[1][4], sn4, d1);
                d2 = fma2(sm[2][4], sn4, d2); d3 = fma2(sm[3][4], sn4, d3);
                d0 = fma2(sm[0][5], sn5, d0); d1 = fma2(sm[1][5], sn5, d1);
                d2 = fma2(sm[2][5], sn5, d2); d3 = fma2(sm[3][5], sn5, d3);
                d0 = fma2(sm[0][6], sn6, d0); d1 = fma2(sm[1][6], sn6, d1);
                d2 = fma2(sm[2][6], sn6, d2); d3 = fma2(sm[3][6], sn6, d3);
                d0 = fma2(sm[0][7], sn7, d0); d1 = fma2(sm[1][7], sn7, d1);
                d2 = fma2(sm[2][7], sn7, d2); d3 = fma2(sm[3][7], sn7, d3);

                acc0 = fma2(pk2(w.x, w.x), d0, acc0);
                acc1 = fma2(pk2(w.y, w.y), d1, acc1);
                acc2 = fma2(pk2(w.z, w.z), d2, acc2);
                acc3 = fma2(pk2(w.w, w.w), d3, acc3);
                den0 = add2(den0, pk2(w.x, w.y));
                den1 = add2(den1, pk2(w.z, w.w));
            }
        }
    }

    float tnum = (hsum2(acc0) + hsum2(acc1)) + (hsum2(acc2) + hsum2(acc3));
    float tden = hsum2(den0) + hsum2(den1);

    // Block reduction -> one double atomic per block
    __shared__ float rn[256], rd[256];
    int t = threadIdx.x;
    __syncthreads(); // sh tile readers done before reusing barrier pattern
    rn[t] = tnum; rd[t] = tden;
    __syncthreads();
#pragma unroll
    for (int s = 128; s > 0; s >>= 1) {
        if (t < s) { rn[t] += rn[t + s]; rd[t] += rd[t + s]; }
        __syncthreads();
    }
    if (t == 0) {
        atomicAdd(&g_num, (double)rn[0]);
        atomicAdd(&g_den, (double)rd[0]);
    }
}

// ---------------------------------------------------------------------------
// Finalize: loss = -(num/den) + sqrt(sum_b ||StS_b - I||_F^2) / B
// ---------------------------------------------------------------------------
__global__ void finalize_kernel(float* __restrict__ out, int loss_idx) {
    int t = threadIdx.x; // 0..255 == (k,j) pair
    int k = t >> 4, j = t & 15;
    float s = 0.f;
#pragma unroll
    for (int b = 0; b < BB; b++) {
        float v = (float)g_StS[b * 256 + t];
        float diff = v - (k == j ? 1.0f : 0.0f);
        s += diff * diff;
    }
    __shared__ float red[256];
    red[t] = s;
    __syncthreads();
#pragma unroll
    for (int st = 128; st > 0; st >>= 1) {
        if (t < st) red[t] += red[t + st];
        __syncthreads();
    }
    if (t == 0) {
        float ortho = sqrtf(red[0]) / (float)BB;
        float cut_loss = (float)(g_num / g_den);
        out[loss_idx] = -cut_loss + ortho;
    }
}

// ---------------------------------------------------------------------------
// Launch
// ---------------------------------------------------------------------------
extern "C" void kernel_launch(void* const* d_in, const int* in_sizes, int n_in,
                              void* d_out, int out_size) {
    const float* W = nullptr;
    const float* logits = nullptr;
    for (int i = 0; i < n_in; i++) {
        long sz = (long)in_sizes[i];
        if (sz == (long)BB * NN * NN)      W      = (const float*)d_in[i];
        else if (sz == (long)BB * NN * KK) logits = (const float*)d_in[i];
        // features [B,N,D] is unused by the reference computation
    }
    float* out = (float*)d_out;

    bool want_S    = (out_size >= BNK);
    bool want_loss = (out_size == 1) || (out_size == BNK + 1);

    zero_kernel<<<1, 1024>>>();
    softmax_kernel<<<(BB * NN) / 256, 256>>>(logits, want_S ? out : nullptr);
    if (want_loss) {
        sts_kernel<<<dim3(BB, 16), 256>>>();
        w_pass_kernel<<<dim3(NN / 1024, NN / 256, BB), 256>>>(W);
        finalize_kernel<<<1, 256>>>(out, (out_size == 1) ? 0 : BNK);
    }
}

// round 8
// speedup vs baseline: 1.4823x; 1.0003x over previous
#include <cuda_runtime.h>
#include <math.h>
#include <stdint.h>

// Problem constants
#define BB 4
#define NN 8192
#define KK 16
#define BNK (BB * NN * KK)   // 524288

// ---------------------------------------------------------------------------
// Device scratch (no allocations allowed)
// ---------------------------------------------------------------------------
__device__ float  g_S[BNK];            // softmax(logits)
__device__ double g_StS[BB * KK * KK]; // per-batch S^T S
__device__ double g_num;               // sum W[n,m] * dot(S_n, S_m)
__device__ double g_den;               // sum W

// ---------------------------------------------------------------------------
// Packed f32x2 helpers (FFMA2 path — ptxas won't emit these from plain C++)
// ---------------------------------------------------------------------------
typedef unsigned long long u64p; // carrier for packed 2 x fp32

__device__ __forceinline__ u64p pk2(float lo, float hi) {
    u64p d;
    asm("mov.b64 %0, {%1, %2};" : "=l"(d) : "f"(lo), "f"(hi));
    return d;
}
__device__ __forceinline__ u64p mul2(u64p a, u64p b) {
    u64p d;
    asm("mul.rn.f32x2 %0, %1, %2;" : "=l"(d) : "l"(a), "l"(b));
    return d;
}
__device__ __forceinline__ u64p fma2(u64p a, u64p b, u64p c) {
    u64p d;
    asm("fma.rn.f32x2 %0, %1, %2, %3;" : "=l"(d) : "l"(a), "l"(b), "l"(c));
    return d;
}
__device__ __forceinline__ u64p add2(u64p a, u64p b) {
    u64p d;
    asm("add.rn.f32x2 %0, %1, %2;" : "=l"(d) : "l"(a), "l"(b));
    return d;
}
__device__ __forceinline__ float hsum2(u64p d) {
    float lo, hi;
    asm("mov.b64 {%0, %1}, %2;" : "=f"(lo), "=f"(hi) : "l"(d));
    return lo + hi;
}

// ---------------------------------------------------------------------------
// Zero the scalar/StS accumulators (fresh each call — deterministic)
// ---------------------------------------------------------------------------
__global__ void zero_kernel() {
    int t = threadIdx.x;
    if (t < BB * KK * KK) g_StS[t] = 0.0;
    if (t == 0) { g_num = 0.0; g_den = 0.0; }
}

// ---------------------------------------------------------------------------
// Softmax over K=16 per row. One thread per row.
// ---------------------------------------------------------------------------
__global__ void softmax_kernel(const float* __restrict__ logits,
                               float* __restrict__ outS) {
    int row = blockIdx.x * blockDim.x + threadIdx.x; // 0 .. B*N-1
    const float4* lp = (const float4*)(logits + (size_t)row * KK);
    float4 v0 = lp[0], v1 = lp[1], v2 = lp[2], v3 = lp[3];
    float v[16] = { v0.x, v0.y, v0.z, v0.w, v1.x, v1.y, v1.z, v1.w,
                    v2.x, v2.y, v2.z, v2.w, v3.x, v3.y, v3.z, v3.w };
    float mx = v[0];
#pragma unroll
    for (int i = 1; i < 16; i++) mx = fmaxf(mx, v[i]);
    float s = 0.f;
#pragma unroll
    for (int i = 0; i < 16; i++) { v[i] = expf(v[i] - mx); s += v[i]; }
    float inv = 1.0f / s;
    float4 o0 = make_float4(v[0]*inv,  v[1]*inv,  v[2]*inv,  v[3]*inv);
    float4 o1 = make_float4(v[4]*inv,  v[5]*inv,  v[6]*inv,  v[7]*inv);
    float4 o2 = make_float4(v[8]*inv,  v[9]*inv,  v[10]*inv, v[11]*inv);
    float4 o3 = make_float4(v[12]*inv, v[13]*inv, v[14]*inv, v[15]*inv);
    float4* sp = (float4*)(g_S + (size_t)row * KK);
    sp[0] = o0; sp[1] = o1; sp[2] = o2; sp[3] = o3;
    if (outS) {
        float4* op = (float4*)(outS + (size_t)row * KK);
        op[0] = o0; op[1] = o1; op[2] = o2; op[3] = o3;
    }
}

// ---------------------------------------------------------------------------
// StS[b,k,j] = sum_n S[b,n,k] * S[b,n,j].
// ---------------------------------------------------------------------------
__global__ void sts_kernel() {
    int b = blockIdx.x;
    int part = blockIdx.y;
    int t = threadIdx.x;
    int k = t >> 4, j = t & 15;
    __shared__ float sh[128 * 16];
    double tot = 0.0;
    int nbeg = part * 512, nend = nbeg + 512;
    for (int n0 = nbeg; n0 < nend; n0 += 128) {
        const float4* src = (const float4*)(g_S + ((size_t)b * NN + n0) * KK);
        float4* dst = (float4*)sh;
        dst[t]       = src[t];
        dst[t + 256] = src[t + 256];
        __syncthreads();
        float acc = 0.f;
#pragma unroll 8
        for (int r = 0; r < 128; r++)
            acc = fmaf(sh[r * 16 + k], sh[r * 16 + j], acc);
        tot += (double)acc;
        __syncthreads();
    }
    atomicAdd(&g_StS[b * 256 + t], tot);
}

// ---------------------------------------------------------------------------
// Main streaming pass over W:
//   num += W[b,n,m] * dot16(S[b,n,:], S[b,m,:]);  den += W[b,n,m]
//
// Block: 256 threads = 8 warps. Each thread owns 4 consecutive columns m
// (S_m pre-packed in 64 regs). ALL warps of a block share the same rows n:
// S_n rows are staged in an 8KB shared tile (broadcast LDS, no L1/L2 reload,
// shared across the 8 warps). Inner loop front-batches W for 4 rows
// (4 independent LDG.128 -> MLP=4 per warp) before computing them.
// Grid: (N/1024 col strips, N/256 row groups, B) = (8, 32, 4) = 1024 blocks.
// ---------------------------------------------------------------------------
__global__ void __launch_bounds__(256, 2)
w_pass_kernel(const float* __restrict__ W) {
    __shared__ float sh[128 * 16];      // one 128-row S tile, 8KB
    const int lane = threadIdx.x & 31;
    const int warp = threadIdx.x >> 5;
    const int b  = blockIdx.z;
    const int c0 = (blockIdx.x * 8 + warp) * 128 + lane * 4; // 4 columns m
    const int r0 = blockIdx.y * 256;                          // 256 rows, 2 tiles

    // Pre-pack S_m for this thread's 4 columns: 4 x 8 packed pairs (64 regs)
    u64p sm[4][8];
#pragma unroll
    for (int jj = 0; jj < 4; jj++) {
        const float4* sp = (const float4*)(g_S + ((size_t)b * NN + (c0 + jj)) * KK);
        float4 a = __ldg(sp), b4 = __ldg(sp + 1), c = __ldg(sp + 2), d = __ldg(sp + 3);
        sm[jj][0] = pk2(a.x, a.y);   sm[jj][1] = pk2(a.z, a.w);
        sm[jj][2] = pk2(b4.x, b4.y); sm[jj][3] = pk2(b4.z, b4.w);
        sm[jj][4] = pk2(c.x, c.y);   sm[jj][5] = pk2(c.z, c.w);
        sm[jj][6] = pk2(d.x, d.y);   sm[jj][7] = pk2(d.z, d.w);
    }

    u64p acc0 = 0, acc1 = 0, acc2 = 0, acc3 = 0; // packed num accumulators
    u64p den0 = 0, den1 = 0;                     // packed den accumulators

#pragma unroll 1
    for (int tile = 0; tile < 2; tile++) {
        const int rbase = r0 + tile * 128;
        __syncthreads(); // protect sh from previous tile's readers
        {
            const float4* src = (const float4*)(g_S + ((size_t)b * NN + rbase) * KK);
            float4* dst = (float4*)sh;
            dst[threadIdx.x]       = src[threadIdx.x];
            dst[threadIdx.x + 256] = src[threadIdx.x + 256];
        }
        __syncthreads();

        const float* Wp = W + ((size_t)b * NN + rbase) * NN + c0;

#pragma unroll 1
        for (int r = 0; r < 128; r += 4) {
            // Front-batched independent W loads: MLP = 4 per warp
            float4 w0 = __ldg((const float4*)(Wp));
            float4 w1 = __ldg((const float4*)(Wp + (size_t)NN));
            float4 w2 = __ldg((const float4*)(Wp + 2 * (size_t)NN));
            float4 w3 = __ldg((const float4*)(Wp + 3 * (size_t)NN));
            Wp += 4 * (size_t)NN;

#pragma unroll
            for (int j = 0; j < 4; j++) {
                float4 w = (j == 0) ? w0 : (j == 1) ? w1 : (j == 2) ? w2 : w3;
                const float4* sp = (const float4*)(sh + (size_t)(r + j) * KK);
                float4 a = sp[0], e = sp[1], c = sp[2], d = sp[3]; // broadcast LDS
                u64p sn0 = pk2(a.x, a.y), sn1 = pk2(a.z, a.w);
                u64p sn2 = pk2(e.x, e.y), sn3 = pk2(e.z, e.w);
                u64p sn4 = pk2(c.x, c.y), sn5 = pk2(c.z, c.w);
                u64p sn6 = pk2(d.x, d.y), sn7 = pk2(d.z, d.w);

                // 4 independent packed dot chains (ILP = 4)
                u64p d0 = mul2(sm[0][0], sn0);
                u64p d1 = mul2(sm[1][0], sn0);
                u64p d2 = mul2(sm[2][0], sn0);
                u64p d3 = mul2(sm[3][0], sn0);
                d0 = fma2(sm[0][1], sn1, d0); d1 = fma2(sm[1][1], sn1, d1);
                d2 = fma2(sm[2][1], sn1, d2); d3 = fma2(sm[3][1], sn1, d3);
                d0 = fma2(sm[0][2], sn2, d0); d1 = fma2(sm[1][2], sn2, d1);
                d2 = fma2(sm[2][2], sn2, d2); d3 = fma2(sm[3][2], sn2, d3);
                d0 = fma2(sm[0][3], sn3, d0); d1 = fma2(sm[1][3], sn3, d1);
                d2 = fma2(sm[2][3], sn3, d2); d3 = fma2(sm[3][3], sn3, d3);
                d0 = fma2(sm[0][4], sn4, d0); d1 = fma2(sm[1][4], sn4, d1);
                d2 = fma2(sm[2][4], sn4, d2); d3 = fma2(sm[3][4], sn4, d3);
                d0 = fma2(sm[0][5], sn5, d0); d1 = fma2(sm[1][5], sn5, d1);
                d2 = fma2(sm[2][5], sn5, d2); d3 = fma2(sm[3][5], sn5, d3);
                d0 = fma2(sm[0][6], sn6, d0); d1 = fma2(sm[1][6], sn6, d1);
                d2 = fma2(sm[2][6], sn6, d2); d3 = fma2(sm[3][6], sn6, d3);
                d0 = fma2(sm[0][7], sn7, d0); d1 = fma2(sm[1][7], sn7, d1);
                d2 = fma2(sm[2][7], sn7, d2); d3 = fma2(sm[3][7], sn7, d3);

                acc0 = fma2(pk2(w.x, w.x), d0, acc0);
                acc1 = fma2(pk2(w.y, w.y), d1, acc1);
                acc2 = fma2(pk2(w.z, w.z), d2, acc2);
                acc3 = fma2(pk2(w.w, w.w), d3, acc3);
                den0 = add2(den0, pk2(w.x, w.y));
                den1 = add2(den1, pk2(w.z, w.w));
            }
        }
    }

    float tnum = (hsum2(acc0) + hsum2(acc1)) + (hsum2(acc2) + hsum2(acc3));
    float tden = hsum2(den0) + hsum2(den1);

    // Block reduction -> one double atomic per block
    __shared__ float rn[256], rd[256];
    int t = threadIdx.x;
    __syncthreads(); // sh tile readers done before reusing barrier pattern
    rn[t] = tnum; rd[t] = tden;
    __syncthreads();
#pragma unroll
    for (int s = 128; s > 0; s >>= 1) {
        if (t < s) { rn[t] += rn[t + s]; rd[t] += rd[t + s]; }
        __syncthreads();
    }
    if (t == 0) {
        atomicAdd(&g_num, (double)rn[0]);
        atomicAdd(&g_den, (double)rd[0]);
    }
}

// ---------------------------------------------------------------------------
// Finalize: loss = -(num/den) + sqrt(sum_b ||StS_b - I||_F^2) / B
// ---------------------------------------------------------------------------
__global__ void finalize_kernel(float* __restrict__ out, int loss_idx) {
    int t = threadIdx.x; // 0..255 == (k,j) pair
    int k = t >> 4, j = t & 15;
    float s = 0.f;
#pragma unroll
    for (int b = 0; b < BB; b++) {
        float v = (float)g_StS[b * 256 + t];
        float diff = v - (k == j ? 1.0f : 0.0f);
        s += diff * diff;
    }
    __shared__ float red[256];
    red[t] = s;
    __syncthreads();
#pragma unroll
    for (int st = 128; st > 0; st >>= 1) {
        if (t < st) red[t] += red[t + st];
        __syncthreads();
    }
    if (t == 0) {
        float ortho = sqrtf(red[0]) / (float)BB;
        float cut_loss = (float)(g_num / g_den);
        out[loss_idx] = -cut_loss + ortho;
    }
}

// ---------------------------------------------------------------------------
// Launch
// ---------------------------------------------------------------------------
extern "C" void kernel_launch(void* const* d_in, const int* in_sizes, int n_in,
                              void* d_out, int out_size) {
    const float* W = nullptr;
    const float* logits = nullptr;
    for (int i = 0; i < n_in; i++) {
        long sz = (long)in_sizes[i];
        if (sz == (long)BB * NN * NN)      W      = (const float*)d_in[i];
        else if (sz == (long)BB * NN * KK) logits = (const float*)d_in[i];
        // features [B,N,D] is unused by the reference computation
    }
    float* out = (float*)d_out;

    bool want_S    = (out_size >= BNK);
    bool want_loss = (out_size == 1) || (out_size == BNK + 1);

    zero_kernel<<<1, 1024>>>();
    softmax_kernel<<<(BB * NN) / 256, 256>>>(logits, want_S ? out : nullptr);
    if (want_loss) {
        sts_kernel<<<dim3(BB, 16), 256>>>();
        w_pass_kernel<<<dim3(NN / 1024, NN / 256, BB), 256>>>(W);
        finalize_kernel<<<1, 256>>>(out, (out_size == 1) ? 0 : BNK);
    }
}

// round 10
// speedup vs baseline: 1.7122x; 1.1551x over previous
#include <cuda_runtime.h>
#include <math.h>
#include <stdint.h>

// Problem constants
#define BB 4
#define NN 8192
#define KK 16
#define BNK (BB * NN * KK)   // 524288

// ---------------------------------------------------------------------------
// Device scratch (no allocations allowed)
// ---------------------------------------------------------------------------
__device__ float  g_S[BNK];            // softmax(logits)
__device__ double g_StS[BB * KK * KK]; // per-batch S^T S (1024 doubles)
__device__ double g_num;               // sum W[n,m] * dot(S_n, S_m)
__device__ double g_den;               // sum W

// ---------------------------------------------------------------------------
// Packed f32x2 helpers (FFMA2 path — ptxas won't emit these from plain C++)
// ---------------------------------------------------------------------------
typedef unsigned long long u64p; // carrier for packed 2 x fp32

__device__ __forceinline__ u64p pk2(float lo, float hi) {
    u64p d;
    asm("mov.b64 %0, {%1, %2};" : "=l"(d) : "f"(lo), "f"(hi));
    return d;
}
__device__ __forceinline__ u64p mul2(u64p a, u64p b) {
    u64p d;
    asm("mul.rn.f32x2 %0, %1, %2;" : "=l"(d) : "l"(a), "l"(b));
    return d;
}
__device__ __forceinline__ u64p fma2(u64p a, u64p b, u64p c) {
    u64p d;
    asm("fma.rn.f32x2 %0, %1, %2, %3;" : "=l"(d) : "l"(a), "l"(b), "l"(c));
    return d;
}
__device__ __forceinline__ u64p add2(u64p a, u64p b) {
    u64p d;
    asm("add.rn.f32x2 %0, %1, %2;" : "=l"(d) : "l"(a), "l"(b));
    return d;
}
__device__ __forceinline__ float hsum2(u64p d) {
    float lo, hi;
    asm("mov.b64 {%0, %1}, %2;" : "=f"(lo), "=f"(hi) : "l"(d));
    return lo + hi;
}

// ---------------------------------------------------------------------------
// cp.async helpers (L1-bypass 16B copies; per-thread group tracking)
// ---------------------------------------------------------------------------
__device__ __forceinline__ void cp_async16(uint32_t smem_addr, const void* gptr) {
    asm volatile("cp.async.cg.shared.global [%0], [%1], 16;"
                 :: "r"(smem_addr), "l"(gptr) : "memory");
}
#define CP_COMMIT() asm volatile("cp.async.commit_group;" ::: "memory")
#define CP_WAIT1()  asm volatile("cp.async.wait_group 1;" ::: "memory")

// ---------------------------------------------------------------------------
// Softmax over K=16 per row. One thread per row. Block 0 also zeroes ALL
// accumulators (strided loop: 1024 StS entries > 256 threads — the R9 bug).
// Consumers (sts/w_pass/finalize) launch strictly later in-stream.
// ---------------------------------------------------------------------------
__global__ void softmax_kernel(const float* __restrict__ logits,
                               float* __restrict__ outS) {
    if (blockIdx.x == 0) {
        int t = threadIdx.x;
        for (int i = t; i < BB * KK * KK; i += 256) g_StS[i] = 0.0;
        if (t == 0) { g_num = 0.0; g_den = 0.0; }
    }
    int row = blockIdx.x * blockDim.x + threadIdx.x; // 0 .. B*N-1
    const float4* lp = (const float4*)(logits + (size_t)row * KK);
    float4 v0 = lp[0], v1 = lp[1], v2 = lp[2], v3 = lp[3];
    float v[16] = { v0.x, v0.y, v0.z, v0.w, v1.x, v1.y, v1.z, v1.w,
                    v2.x, v2.y, v2.z, v2.w, v3.x, v3.y, v3.z, v3.w };
    float mx = v[0];
#pragma unroll
    for (int i = 1; i < 16; i++) mx = fmaxf(mx, v[i]);
    float s = 0.f;
#pragma unroll
    for (int i = 0; i < 16; i++) { v[i] = expf(v[i] - mx); s += v[i]; }
    float inv = 1.0f / s;
    float4 o0 = make_float4(v[0]*inv,  v[1]*inv,  v[2]*inv,  v[3]*inv);
    float4 o1 = make_float4(v[4]*inv,  v[5]*inv,  v[6]*inv,  v[7]*inv);
    float4 o2 = make_float4(v[8]*inv,  v[9]*inv,  v[10]*inv, v[11]*inv);
    float4 o3 = make_float4(v[12]*inv, v[13]*inv, v[14]*inv, v[15]*inv);
    float4* sp = (float4*)(g_S + (size_t)row * KK);
    sp[0] = o0; sp[1] = o1; sp[2] = o2; sp[3] = o3;
    if (outS) {
        float4* op = (float4*)(outS + (size_t)row * KK);
        op[0] = o0; op[1] = o1; op[2] = o2; op[3] = o3;
    }
}

// ---------------------------------------------------------------------------
// StS[b,k,j] = sum_n S[b,n,k] * S[b,n,j].
// ---------------------------------------------------------------------------
__global__ void sts_kernel() {
    int b = blockIdx.x;
    int part = blockIdx.y;
    int t = threadIdx.x;
    int k = t >> 4, j = t & 15;
    __shared__ float sh[128 * 16];
    double tot = 0.0;
    int nbeg = part * 512, nend = nbeg + 512;
    for (int n0 = nbeg; n0 < nend; n0 += 128) {
        const float4* src = (const float4*)(g_S + ((size_t)b * NN + n0) * KK);
        float4* dst = (float4*)sh;
        dst[t]       = src[t];
        dst[t + 256] = src[t + 256];
        __syncthreads();
        float acc = 0.f;
#pragma unroll 8
        for (int r = 0; r < 128; r++)
            acc = fmaf(sh[r * 16 + k], sh[r * 16 + j], acc);
        tot += (double)acc;
        __syncthreads();
    }
    atomicAdd(&g_StS[b * 256 + t], tot);
}

// ---------------------------------------------------------------------------
// Main streaming pass over W:
//   num += W[b,n,m] * dot16(S[b,n,:], S[b,m,:]);  den += W[b,n,m]
//
// Block: 256 threads = 8 warps. Each thread owns 4 consecutive columns m
// (S_m pre-packed in 64 regs). S_n rows staged in an 8KB shared tile.
// W streams through a cp.async.cg double-buffered smem ring: each thread
// copies exactly the 4x16B it alone reads (no barriers, per-thread
// wait_group). While chunk k is computed, chunk k+1 is ALWAYS in flight:
// in-flight bytes/SM = 512thr*64B = 32KB >= BW*latency (~25KB) -> sustained
// DRAM streaming instead of pulsed load/compute phases.
// Grid: (N/1024 col strips, N/256 row groups, B) = (8, 32, 4) = 1024 blocks.
// ---------------------------------------------------------------------------
__global__ void __launch_bounds__(256, 2)
w_pass_kernel(const float* __restrict__ W) {
    __shared__ float4 shW[2][4][256];   // W ring: [slot][row-in-chunk][thread], 32KB
    __shared__ float  shS[128 * 16];    // one 128-row S tile, 8KB
    __shared__ float  rn[256], rd[256]; // reduction, 2KB

    const int tid  = threadIdx.x;
    const int lane = tid & 31;
    const int warp = tid >> 5;
    const int b  = blockIdx.z;
    const int c0 = (blockIdx.x * 8 + warp) * 128 + lane * 4; // 4 columns m
    const int r0 = blockIdx.y * 256;                          // 256 rows, 2 tiles

    // byte address of this thread's 16B slot in shW[0][0]
    const uint32_t swbase =
        (uint32_t)__cvta_generic_to_shared(&shW[0][0][tid]);
    // stride between consecutive [slot][i] planes = 256 * 16 bytes
    const uint32_t plane = 256 * 16;

    // Pre-pack S_m for this thread's 4 columns: 4 x 8 packed pairs (64 regs)
    u64p sm[4][8];
#pragma unroll
    for (int jj = 0; jj < 4; jj++) {
        const float4* sp = (const float4*)(g_S + ((size_t)b * NN + (c0 + jj)) * KK);
        float4 a = __ldg(sp), b4 = __ldg(sp + 1), c = __ldg(sp + 2), d = __ldg(sp + 3);
        sm[jj][0] = pk2(a.x, a.y);   sm[jj][1] = pk2(a.z, a.w);
        sm[jj][2] = pk2(b4.x, b4.y); sm[jj][3] = pk2(b4.z, b4.w);
        sm[jj][4] = pk2(c.x, c.y);   sm[jj][5] = pk2(c.z, c.w);
        sm[jj][6] = pk2(d.x, d.y);   sm[jj][7] = pk2(d.z, d.w);
    }

    u64p acc0 = 0, acc1 = 0, acc2 = 0, acc3 = 0; // packed num accumulators
    u64p den0 = 0, den1 = 0;                     // packed den accumulators

#pragma unroll 1
    for (int tile = 0; tile < 2; tile++) {
        const int rbase = r0 + tile * 128;
        __syncthreads(); // protect shS from previous tile's readers
        {
            const float4* src = (const float4*)(g_S + ((size_t)b * NN + rbase) * KK);
            float4* dst = (float4*)shS;
            dst[tid]       = src[tid];
            dst[tid + 256] = src[tid + 256];
        }
        __syncthreads();

        const float* Wp = W + ((size_t)b * NN + rbase) * NN + c0;

        // Prologue: chunk 0 into slot 0
#pragma unroll
        for (int i = 0; i < 4; i++)
            cp_async16(swbase + (uint32_t)i * plane, Wp + (size_t)i * NN);
        CP_COMMIT();

#pragma unroll 1
        for (int k = 0; k < 32; k++) {        // 32 chunks x 4 rows
            const int slot = k & 1;
            // Issue chunk k+1 into the other slot (empty commit on last iter
            // keeps the group count exact so wait_group 1 drains chunk k).
            if (k + 1 < 32) {
                const float* p = Wp + (size_t)(k + 1) * 4 * NN;
                const uint32_t sb = swbase + (uint32_t)(slot ^ 1) * 4 * plane;
#pragma unroll
                for (int i = 0; i < 4; i++)
                    cp_async16(sb + (uint32_t)i * plane, p + (size_t)i * NN);
            }
            CP_COMMIT();
            CP_WAIT1();   // chunk k resident

#pragma unroll
            for (int i = 0; i < 4; i++) {
                float4 w = shW[slot][i][tid];
                const float4* sp = (const float4*)(shS + (size_t)(k * 4 + i) * KK);
                float4 a = sp[0], e = sp[1], c = sp[2], d = sp[3]; // broadcast LDS
                u64p sn0 = pk2(a.x, a.y), sn1 = pk2(a.z, a.w);
                u64p sn2 = pk2(e.x, e.y), sn3 = pk2(e.z, e.w);
                u64p sn4 = pk2(c.x, c.y), sn5 = pk2(c.z, c.w);
                u64p sn6 = pk2(d.x, d.y), sn7 = pk2(d.z, d.w);

                // 4 independent packed dot chains (ILP = 4)
                u64p d0 = mul2(sm[0][0], sn0);
                u64p d1 = mul2(sm[1][0], sn0);
                u64p d2 = mul2(sm[2][0], sn0);
                u64p d3 = mul2(sm[3][0], sn0);
                d0 = fma2(sm[0][1], sn1, d0); d1 = fma2(sm[1][1], sn1, d1);
                d2 = fma2(sm[2][1], sn1, d2); d3 = fma2(sm[3][1], sn1, d3);
                d0 = fma2(sm[0][2], sn2, d0); d1 = fma2(sm[1][2], sn2, d1);
                d2 = fma2(sm[2][2], sn2, d2); d3 = fma2(sm[3][2], sn2, d3);
                d0 = fma2(sm[0][3], sn3, d0); d1 = fma2(sm[1][3], sn3, d1);
                d2 = fma2(sm[2][3], sn3, d2); d3 = fma2(sm[3][3], sn3, d3);
                d0 = fma2(sm[0][4], sn4, d0); d1 = fma2(sm[1][4], sn4, d1);
                d2 = fma2(sm[2][4], sn4, d2); d3 = fma2(sm[3][4], sn4, d3);
                d0 = fma2(sm[0][5], sn5, d0); d1 = fma2(sm[1][5], sn5, d1);
                d2 = fma2(sm[2][5], sn5, d2); d3 = fma2(sm[3][5], sn5, d3);
                d0 = fma2(sm[0][6], sn6, d0); d1 = fma2(sm[1][6], sn6, d1);
                d2 = fma2(sm[2][6], sn6, d2); d3 = fma2(sm[3][6], sn6, d3);
                d0 = fma2(sm[0][7], sn7, d0); d1 = fma2(sm[1][7], sn7, d1);
                d2 = fma2(sm[2][7], sn7, d2); d3 = fma2(sm[3][7], sn7, d3);

                acc0 = fma2(pk2(w.x, w.x), d0, acc0);
                acc1 = fma2(pk2(w.y, w.y), d1, acc1);
                acc2 = fma2(pk2(w.z, w.z), d2, acc2);
                acc3 = fma2(pk2(w.w, w.w), d3, acc3);
                den0 = add2(den0, pk2(w.x, w.y));
                den1 = add2(den1, pk2(w.z, w.w));
            }
        }
    }

    float tnum = (hsum2(acc0) + hsum2(acc1)) + (hsum2(acc2) + hsum2(acc3));
    float tden = hsum2(den0) + hsum2(den1);

    // Block reduction -> one double atomic per block
    __syncthreads();
    rn[tid] = tnum; rd[tid] = tden;
    __syncthreads();
#pragma unroll
    for (int s = 128; s > 0; s >>= 1) {
        if (tid < s) { rn[tid] += rn[tid + s]; rd[tid] += rd[tid + s]; }
        __syncthreads();
    }
    if (tid == 0) {
        atomicAdd(&g_num, (double)rn[0]);
        atomicAdd(&g_den, (double)rd[0]);
    }
}

// ---------------------------------------------------------------------------
// Finalize: loss = -(num/den) + sqrt(sum_b ||StS_b - I||_F^2) / B
// ---------------------------------------------------------------------------
__global__ void finalize_kernel(float* __restrict__ out, int loss_idx) {
    int t = threadIdx.x; // 0..255 == (k,j) pair
    int k = t >> 4, j = t & 15;
    float s = 0.f;
#pragma unroll
    for (int b = 0; b < BB; b++) {
        float v = (float)g_StS[b * 256 + t];
        float diff = v - (k == j ? 1.0f : 0.0f);
        s += diff * diff;
    }
    __shared__ float red[256];
    red[t] = s;
    __syncthreads();
#pragma unroll
    for (int st = 128; st > 0; st >>= 1) {
        if (t < st) red[t] += red[t + st];
        __syncthreads();
    }
    if (t == 0) {
        float ortho = sqrtf(red[0]) / (float)BB;
        float cut_loss = (float)(g_num / g_den);
        out[loss_idx] = -cut_loss + ortho;
    }
}

// ---------------------------------------------------------------------------
// Launch
// ---------------------------------------------------------------------------
extern "C" void kernel_launch(void* const* d_in, const int* in_sizes, int n_in,
                              void* d_out, int out_size) {
    const float* W = nullptr;
    const float* logits = nullptr;
    for (int i = 0; i < n_in; i++) {
        long sz = (long)in_sizes[i];
        if (sz == (long)BB * NN * NN)      W      = (const float*)d_in[i];
        else if (sz == (long)BB * NN * KK) logits = (const float*)d_in[i];
        // features [B,N,D] is unused by the reference computation
    }
    float* out = (float*)d_out;

    bool want_S    = (out_size >= BNK);
    bool want_loss = (out_size == 1) || (out_size == BNK + 1);

    softmax_kernel<<<(BB * NN) / 256, 256>>>(logits, want_S ? out : nullptr);
    if (want_loss) {
        sts_kernel<<<dim3(BB, 16), 256>>>();
        w_pass_kernel<<<dim3(NN / 1024, NN / 256, BB), 256>>>(W);
        finalize_kernel<<<1, 256>>>(out, (out_size == 1) ? 0 : BNK);
    }
}

// round 11
// speedup vs baseline: 1.7220x; 1.0057x over previous
#include <cuda_runtime.h>
#include <math.h>
#include <stdint.h>

// Problem constants
#define BB 4
#define NN 8192
#define KK 16
#define BNK (BB * NN * KK)   // 524288

// ---------------------------------------------------------------------------
// Device scratch (no allocations allowed)
// ---------------------------------------------------------------------------
__device__ float  g_S[BNK];            // softmax(logits)
__device__ double g_StS[BB * KK * KK]; // per-batch S^T S (1024 doubles)
__device__ double g_num;               // sum W[n,m] * dot(S_n, S_m)
__device__ double g_den;               // sum W

// ---------------------------------------------------------------------------
// Packed f32x2 helpers (FFMA2 path — ptxas won't emit these from plain C++)
// ---------------------------------------------------------------------------
typedef unsigned long long u64p; // carrier for packed 2 x fp32

__device__ __forceinline__ u64p pk2(float lo, float hi) {
    u64p d;
    asm("mov.b64 %0, {%1, %2};" : "=l"(d) : "f"(lo), "f"(hi));
    return d;
}
__device__ __forceinline__ u64p mul2(u64p a, u64p b) {
    u64p d;
    asm("mul.rn.f32x2 %0, %1, %2;" : "=l"(d) : "l"(a), "l"(b));
    return d;
}
__device__ __forceinline__ u64p fma2(u64p a, u64p b, u64p c) {
    u64p d;
    asm("fma.rn.f32x2 %0, %1, %2, %3;" : "=l"(d) : "l"(a), "l"(b), "l"(c));
    return d;
}
__device__ __forceinline__ u64p add2(u64p a, u64p b) {
    u64p d;
    asm("add.rn.f32x2 %0, %1, %2;" : "=l"(d) : "l"(a), "l"(b));
    return d;
}
__device__ __forceinline__ float hsum2(u64p d) {
    float lo, hi;
    asm("mov.b64 {%0, %1}, %2;" : "=f"(lo), "=f"(hi) : "l"(d));
    return lo + hi;
}

// ---------------------------------------------------------------------------
// cp.async helpers (L1-bypass 16B copies; per-thread group tracking)
// ---------------------------------------------------------------------------
__device__ __forceinline__ void cp_async16(uint32_t smem_addr, const void* gptr) {
    asm volatile("cp.async.cg.shared.global [%0], [%1], 16;"
                 :: "r"(smem_addr), "l"(gptr) : "memory");
}
#define CP_COMMIT() asm volatile("cp.async.commit_group;" ::: "memory")
#define CP_WAIT1()  asm volatile("cp.async.wait_group 1;" ::: "memory")

// ---------------------------------------------------------------------------
// Softmax over K=16 per row. One thread per row. Block 0 also zeroes ALL
// accumulators (strided loop: 1024 StS entries > 256 threads — the R9 bug).
// Consumers (sts/w_pass/finalize) launch strictly later in-stream.
// ---------------------------------------------------------------------------
__global__ void softmax_kernel(const float* __restrict__ logits,
                               float* __restrict__ outS) {
    if (blockIdx.x == 0) {
        int t = threadIdx.x;
        for (int i = t; i < BB * KK * KK; i += 256) g_StS[i] = 0.0;
        if (t == 0) { g_num = 0.0; g_den = 0.0; }
    }
    int row = blockIdx.x * blockDim.x + threadIdx.x; // 0 .. B*N-1
    const float4* lp = (const float4*)(logits + (size_t)row * KK);
    float4 v0 = lp[0], v1 = lp[1], v2 = lp[2], v3 = lp[3];
    float v[16] = { v0.x, v0.y, v0.z, v0.w, v1.x, v1.y, v1.z, v1.w,
                    v2.x, v2.y, v2.z, v2.w, v3.x, v3.y, v3.z, v3.w };
    float mx = v[0];
#pragma unroll
    for (int i = 1; i < 16; i++) mx = fmaxf(mx, v[i]);
    float s = 0.f;
#pragma unroll
    for (int i = 0; i < 16; i++) { v[i] = expf(v[i] - mx); s += v[i]; }
    float inv = 1.0f / s;
    float4 o0 = make_float4(v[0]*inv,  v[1]*inv,  v[2]*inv,  v[3]*inv);
    float4 o1 = make_float4(v[4]*inv,  v[5]*inv,  v[6]*inv,  v[7]*inv);
    float4 o2 = make_float4(v[8]*inv,  v[9]*inv,  v[10]*inv, v[11]*inv);
    float4 o3 = make_float4(v[12]*inv, v[13]*inv, v[14]*inv, v[15]*inv);
    float4* sp = (float4*)(g_S + (size_t)row * KK);
    sp[0] = o0; sp[1] = o1; sp[2] = o2; sp[3] = o3;
    if (outS) {
        float4* op = (float4*)(outS + (size_t)row * KK);
        op[0] = o0; op[1] = o1; op[2] = o2; op[3] = o3;
    }
}

// ---------------------------------------------------------------------------
// StS[b,k,j] = sum_n S[b,n,k] * S[b,n,j].
// ---------------------------------------------------------------------------
__global__ void sts_kernel() {
    int b = blockIdx.x;
    int part = blockIdx.y;
    int t = threadIdx.x;
    int k = t >> 4, j = t & 15;
    __shared__ float sh[128 * 16];
    double tot = 0.0;
    int nbeg = part * 512, nend = nbeg + 512;
    for (int n0 = nbeg; n0 < nend; n0 += 128) {
        const float4* src = (const float4*)(g_S + ((size_t)b * NN + n0) * KK);
        float4* dst = (float4*)sh;
        dst[t]       = src[t];
        dst[t + 256] = src[t + 256];
        __syncthreads();
        float acc = 0.f;
#pragma unroll 8
        for (int r = 0; r < 128; r++)
            acc = fmaf(sh[r * 16 + k], sh[r * 16 + j], acc);
        tot += (double)acc;
        __syncthreads();
    }
    atomicAdd(&g_StS[b * 256 + t], tot);
}

// ---------------------------------------------------------------------------
// Main streaming pass over W:
//   num += W[b,n,m] * dot16(S[b,n,:], S[b,m,:]);  den += W[b,n,m]
//
// Block: 256 threads = 8 warps. Each thread owns 4 consecutive columns m
// (S_m pre-packed in 64 regs). S_n rows staged in an 8KB shared tile.
// W streams through a cp.async.cg double-buffered smem ring: each thread
// copies exactly the 4x16B it alone reads (no barriers, per-thread
// wait_group). While chunk k is computed, chunk k+1 is ALWAYS in flight:
// in-flight bytes/SM = 512thr*64B = 32KB >= BW*latency (~25KB) -> sustained
// DRAM streaming instead of pulsed load/compute phases.
// Grid: (N/1024 col strips, N/256 row groups, B) = (8, 32, 4) = 1024 blocks.
// ---------------------------------------------------------------------------
__global__ void __launch_bounds__(256, 2)
w_pass_kernel(const float* __restrict__ W) {
    __shared__ float4 shW[2][4][256];   // W ring: [slot][row-in-chunk][thread], 32KB
    __shared__ float  shS[128 * 16];    // one 128-row S tile, 8KB
    __shared__ float  rn[256], rd[256]; // reduction, 2KB

    const int tid  = threadIdx.x;
    const int lane = tid & 31;
    const int warp = tid >> 5;
    const int b  = blockIdx.z;
    const int c0 = (blockIdx.x * 8 + warp) * 128 + lane * 4; // 4 columns m
    const int r0 = blockIdx.y * 256;                          // 256 rows, 2 tiles

    // byte address of this thread's 16B slot in shW[0][0]
    const uint32_t swbase =
        (uint32_t)__cvta_generic_to_shared(&shW[0][0][tid]);
    // stride between consecutive [slot][i] planes = 256 * 16 bytes
    const uint32_t plane = 256 * 16;

    // Pre-pack S_m for this thread's 4 columns: 4 x 8 packed pairs (64 regs)
    u64p sm[4][8];
#pragma unroll
    for (int jj = 0; jj < 4; jj++) {
        const float4* sp = (const float4*)(g_S + ((size_t)b * NN + (c0 + jj)) * KK);
        float4 a = __ldg(sp), b4 = __ldg(sp + 1), c = __ldg(sp + 2), d = __ldg(sp + 3);
        sm[jj][0] = pk2(a.x, a.y);   sm[jj][1] = pk2(a.z, a.w);
        sm[jj][2] = pk2(b4.x, b4.y); sm[jj][3] = pk2(b4.z, b4.w);
        sm[jj][4] = pk2(c.x, c.y);   sm[jj][5] = pk2(c.z, c.w);
        sm[jj][6] = pk2(d.x, d.y);   sm[jj][7] = pk2(d.z, d.w);
    }

    u64p acc0 = 0, acc1 = 0, acc2 = 0, acc3 = 0; // packed num accumulators
    u64p den0 = 0, den1 = 0;                     // packed den accumulators

#pragma unroll 1
    for (int tile = 0; tile < 2; tile++) {
        const int rbase = r0 + tile * 128;
        __syncthreads(); // protect shS from previous tile's readers
        {
            const float4* src = (const float4*)(g_S + ((size_t)b * NN + rbase) * KK);
            float4* dst = (float4*)shS;
            dst[tid]       = src[tid];
            dst[tid + 256] = src[tid + 256];
        }
        __syncthreads();

        const float* Wp = W + ((size_t)b * NN + rbase) * NN + c0;

        // Prologue: chunk 0 into slot 0
#pragma unroll
        for (int i = 0; i < 4; i++)
            cp_async16(swbase + (uint32_t)i * plane, Wp + (size_t)i * NN);
        CP_COMMIT();

#pragma unroll 1
        for (int k = 0; k < 32; k++) {        // 32 chunks x 4 rows
            const int slot = k & 1;
            // Issue chunk k+1 into the other slot (empty commit on last iter
            // keeps the group count exact so wait_group 1 drains chunk k).
            if (k + 1 < 32) {
                const float* p = Wp + (size_t)(k + 1) * 4 * NN;
                const uint32_t sb = swbase + (uint32_t)(slot ^ 1) * 4 * plane;
#pragma unroll
                for (int i = 0; i < 4; i++)
                    cp_async16(sb + (uint32_t)i * plane, p + (size_t)i * NN);
            }
            CP_COMMIT();
            CP_WAIT1();   // chunk k resident

#pragma unroll
            for (int i = 0; i < 4; i++) {
                float4 w = shW[slot][i][tid];
                const float4* sp = (const float4*)(shS + (size_t)(k * 4 + i) * KK);
                float4 a = sp[0], e = sp[1], c = sp[2], d = sp[3]; // broadcast LDS
                u64p sn0 = pk2(a.x, a.y), sn1 = pk2(a.z, a.w);
                u64p sn2 = pk2(e.x, e.y), sn3 = pk2(e.z, e.w);
                u64p sn4 = pk2(c.x, c.y), sn5 = pk2(c.z, c.w);
                u64p sn6 = pk2(d.x, d.y), sn7 = pk2(d.z, d.w);

                // 4 independent packed dot chains (ILP = 4)
                u64p d0 = mul2(sm[0][0], sn0);
                u64p d1 = mul2(sm[1][0], sn0);
                u64p d2 = mul2(sm[2][0], sn0);
                u64p d3 = mul2(sm[3][0], sn0);
                d0 = fma2(sm[0][1], sn1, d0); d1 = fma2(sm[1][1], sn1, d1);
                d2 = fma2(sm[2][1], sn1, d2); d3 = fma2(sm[3][1], sn1, d3);
                d0 = fma2(sm[0][2], sn2, d0); d1 = fma2(sm[1][2], sn2, d1);
                d2 = fma2(sm[2][2], sn2, d2); d3 = fma2(sm[3][2], sn2, d3);
                d0 = fma2(sm[0][3], sn3, d0); d1 = fma2(sm[1][3], sn3, d1);
                d2 = fma2(sm[2][3], sn3, d2); d3 = fma2(sm[3][3], sn3, d3);
                d0 = fma2(sm[0][4], sn4, d0); d1 = fma2(sm[1][4], sn4, d1);
                d2 = fma2(sm[2][4], sn4, d2); d3 = fma2(sm[3][4], sn4, d3);
                d0 = fma2(sm[0][5], sn5, d0); d1 = fma2(sm[1][5], sn5, d1);
                d2 = fma2(sm[2][5], sn5, d2); d3 = fma2(sm[3][5], sn5, d3);
                d0 = fma2(sm[0][6], sn6, d0); d1 = fma2(sm[1][6], sn6, d1);
                d2 = fma2(sm[2][6], sn6, d2); d3 = fma2(sm[3][6], sn6, d3);
                d0 = fma2(sm[0][7], sn7, d0); d1 = fma2(sm[1][7], sn7, d1);
                d2 = fma2(sm[2][7], sn7, d2); d3 = fma2(sm[3][7], sn7, d3);

                acc0 = fma2(pk2(w.x, w.x), d0, acc0);
                acc1 = fma2(pk2(w.y, w.y), d1, acc1);
                acc2 = fma2(pk2(w.z, w.z), d2, acc2);
                acc3 = fma2(pk2(w.w, w.w), d3, acc3);
                den0 = add2(den0, pk2(w.x, w.y));
                den1 = add2(den1, pk2(w.z, w.w));
            }
        }
    }

    float tnum = (hsum2(acc0) + hsum2(acc1)) + (hsum2(acc2) + hsum2(acc3));
    float tden = hsum2(den0) + hsum2(den1);

    // Block reduction -> one double atomic per block
    __syncthreads();
    rn[tid] = tnum; rd[tid] = tden;
    __syncthreads();
#pragma unroll
    for (int s = 128; s > 0; s >>= 1) {
        if (tid < s) { rn[tid] += rn[tid + s]; rd[tid] += rd[tid + s]; }
        __syncthreads();
    }
    if (tid == 0) {
        atomicAdd(&g_num, (double)rn[0]);
        atomicAdd(&g_den, (double)rd[0]);
    }
}

// ---------------------------------------------------------------------------
// Finalize: loss = -(num/den) + sqrt(sum_b ||StS_b - I||_F^2) / B
// ---------------------------------------------------------------------------
__global__ void finalize_kernel(float* __restrict__ out, int loss_idx) {
    int t = threadIdx.x; // 0..255 == (k,j) pair
    int k = t >> 4, j = t & 15;
    float s = 0.f;
#pragma unroll
    for (int b = 0; b < BB; b++) {
        float v = (float)g_StS[b * 256 + t];
        float diff = v - (k == j ? 1.0f : 0.0f);
        s += diff * diff;
    }
    __shared__ float red[256];
    red[t] = s;
    __syncthreads();
#pragma unroll
    for (int st = 128; st > 0; st >>= 1) {
        if (t < st) red[t] += red[t + st];
        __syncthreads();
    }
    if (t == 0) {
        float ortho = sqrtf(red[0]) / (float)BB;
        float cut_loss = (float)(g_num / g_den);
        out[loss_idx] = -cut_loss + ortho;
    }
}

// ---------------------------------------------------------------------------
// Launch
// ---------------------------------------------------------------------------
extern "C" void kernel_launch(void* const* d_in, const int* in_sizes, int n_in,
                              void* d_out, int out_size) {
    const float* W = nullptr;
    const float* logits = nullptr;
    for (int i = 0; i < n_in; i++) {
        long sz = (long)in_sizes[i];
        if (sz == (long)BB * NN * NN)      W      = (const float*)d_in[i];
        else if (sz == (long)BB * NN * KK) logits = (const float*)d_in[i];
        // features [B,N,D] is unused by the reference computation
    }
    float* out = (float*)d_out;

    bool want_S    = (out_size >= BNK);
    bool want_loss = (out_size == 1) || (out_size == BNK + 1);

    softmax_kernel<<<(BB * NN) / 256, 256>>>(logits, want_S ? out : nullptr);
    if (want_loss) {
        sts_kernel<<<dim3(BB, 16), 256>>>();
        w_pass_kernel<<<dim3(NN / 1024, NN / 256, BB), 256>>>(W);
        finalize_kernel<<<1, 256>>>(out, (out_size == 1) ? 0 : BNK);
    }
}

// round 12
// speedup vs baseline: 1.8216x; 1.0579x over previous
#include <cuda_runtime.h>
#include <math.h>
#include <stdint.h>

// Problem constants
#define BB 4
#define NN 8192
#define KK 16
#define BNK (BB * NN * KK)   // 524288

#define W_GRID_BLOCKS (8 * 32 * 4)   // w_pass grid size (x*y*z)
#define DYN_SMEM (4*4*256*16 + 256*16*4 + 2*256*4)  // 65536 + 16384 + 2048 = 83968

// ---------------------------------------------------------------------------
// Device scratch (no allocations allowed)
// ---------------------------------------------------------------------------
__device__ float    g_S[BNK];            // softmax(logits)
__device__ double   g_StS[BB * KK * KK]; // per-batch S^T S (1024 doubles)
__device__ double   g_num;               // sum W[n,m] * dot(S_n, S_m)
__device__ double   g_den;               // sum W
__device__ unsigned g_done;              // finished-block counter

// ---------------------------------------------------------------------------
// Packed f32x2 helpers (FFMA2 path — ptxas won't emit these from plain C++)
// ---------------------------------------------------------------------------
typedef unsigned long long u64p; // carrier for packed 2 x fp32

__device__ __forceinline__ u64p pk2(float lo, float hi) {
    u64p d;
    asm("mov.b64 %0, {%1, %2};" : "=l"(d) : "f"(lo), "f"(hi));
    return d;
}
__device__ __forceinline__ u64p mul2(u64p a, u64p b) {
    u64p d;
    asm("mul.rn.f32x2 %0, %1, %2;" : "=l"(d) : "l"(a), "l"(b));
    return d;
}
__device__ __forceinline__ u64p fma2(u64p a, u64p b, u64p c) {
    u64p d;
    asm("fma.rn.f32x2 %0, %1, %2, %3;" : "=l"(d) : "l"(a), "l"(b), "l"(c));
    return d;
}
__device__ __forceinline__ u64p add2(u64p a, u64p b) {
    u64p d;
    asm("add.rn.f32x2 %0, %1, %2;" : "=l"(d) : "l"(a), "l"(b));
    return d;
}
__device__ __forceinline__ float hsum2(u64p d) {
    float lo, hi;
    asm("mov.b64 {%0, %1}, %2;" : "=f"(lo), "=f"(hi) : "l"(d));
    return lo + hi;
}

// ---------------------------------------------------------------------------
// cp.async helpers (L1-bypass 16B copies; per-thread group tracking)
// ---------------------------------------------------------------------------
__device__ __forceinline__ void cp_async16(uint32_t smem_addr, const void* gptr) {
    asm volatile("cp.async.cg.shared.global [%0], [%1], 16;"
                 :: "r"(smem_addr), "l"(gptr) : "memory");
}
#define CP_COMMIT() asm volatile("cp.async.commit_group;" ::: "memory")
#define CP_WAIT3()  asm volatile("cp.async.wait_group 3;" ::: "memory")

// ---------------------------------------------------------------------------
// Softmax over K=16 per row. One thread per row. Block 0 zeroes ALL
// accumulators (strided — 1024 StS entries > 256 threads).
// ---------------------------------------------------------------------------
__global__ void softmax_kernel(const float* __restrict__ logits,
                               float* __restrict__ outS) {
    if (blockIdx.x == 0) {
        int t = threadIdx.x;
        for (int i = t; i < BB * KK * KK; i += 256) g_StS[i] = 0.0;
        if (t == 0) { g_num = 0.0; g_den = 0.0; }
    }
    int row = blockIdx.x * blockDim.x + threadIdx.x; // 0 .. B*N-1
    const float4* lp = (const float4*)(logits + (size_t)row * KK);
    float4 v0 = lp[0], v1 = lp[1], v2 = lp[2], v3 = lp[3];
    float v[16] = { v0.x, v0.y, v0.z, v0.w, v1.x, v1.y, v1.z, v1.w,
                    v2.x, v2.y, v2.z, v2.w, v3.x, v3.y, v3.z, v3.w };
    float mx = v[0];
#pragma unroll
    for (int i = 1; i < 16; i++) mx = fmaxf(mx, v[i]);
    float s = 0.f;
#pragma unroll
    for (int i = 0; i < 16; i++) { v[i] = expf(v[i] - mx); s += v[i]; }
    float inv = 1.0f / s;
    float4 o0 = make_float4(v[0]*inv,  v[1]*inv,  v[2]*inv,  v[3]*inv);
    float4 o1 = make_float4(v[4]*inv,  v[5]*inv,  v[6]*inv,  v[7]*inv);
    float4 o2 = make_float4(v[8]*inv,  v[9]*inv,  v[10]*inv, v[11]*inv);
    float4 o3 = make_float4(v[12]*inv, v[13]*inv, v[14]*inv, v[15]*inv);
    float4* sp = (float4*)(g_S + (size_t)row * KK);
    sp[0] = o0; sp[1] = o1; sp[2] = o2; sp[3] = o3;
    if (outS) {
        float4* op = (float4*)(outS + (size_t)row * KK);
        op[0] = o0; op[1] = o1; op[2] = o2; op[3] = o3;
    }
}

// ---------------------------------------------------------------------------
// Fused main pass:
//   num += W[b,n,m] * dot16(S_n, S_m);  den += W[b,n,m]
//   + StS partials (blockIdx.x==0 blocks, from the resident shS tile)
//   + finalize (last block writes the loss)
//
// Block: 256 threads = 8 warps. Each thread owns 4 consecutive columns m
// (S_m pre-packed in 64 regs). 256 S_n rows staged once in a 16KB smem tile.
// W streams through a 4-slot cp.async.cg ring, prefetch distance 3: each
// thread copies exactly the 4x16B it alone reads (no barriers, per-thread
// wait_group). In-flight W = 192B/thread = 96KB/SM -> wait_group rarely
// blocks; sustained DRAM streaming.
// Grid: (8 col strips, 32 row groups, B) = 1024 blocks.
// ---------------------------------------------------------------------------
__global__ void __launch_bounds__(256, 2)
w_pass_kernel(const float* __restrict__ W, float* __restrict__ out,
              int loss_idx) {
    extern __shared__ char dyn[];
    // [slot][row-in-chunk][thread] 16B each: 4*4*256*16 = 64KB
    float4* shW = (float4*)dyn;
    float*  shS = (float*)(dyn + 4 * 4 * 256 * 16);   // 256 rows x 16 = 16KB
    float*  rn  = shS + 256 * 16;                     // 1KB
    float*  rd  = rn + 256;                           // 1KB

    const int tid  = threadIdx.x;
    const int lane = tid & 31;
    const int warp = tid >> 5;
    const int b  = blockIdx.z;
    const int c0 = (blockIdx.x * 8 + warp) * 128 + lane * 4; // 4 columns m
    const int r0 = blockIdx.y * 256;                          // 256 rows

    // byte address of this thread's 16B slot in shW plane 0
    const uint32_t swbase = (uint32_t)__cvta_generic_to_shared(&shW[tid]);
    const uint32_t plane  = 256 * 16;          // one row-in-chunk plane
    const uint32_t slotsz = 4 * plane;         // one ring slot (4 rows)

    // Stage 256 S_n rows (16KB) once
    {
        const float4* src = (const float4*)(g_S + ((size_t)b * NN + r0) * KK);
        float4* dst = (float4*)shS;
        dst[tid]       = src[tid];
        dst[tid + 256] = src[tid + 256];
        dst[tid + 512] = src[tid + 512];
        dst[tid + 768] = src[tid + 768];
    }

    // Pre-pack S_m for this thread's 4 columns: 4 x 8 packed pairs (64 regs)
    u64p sm[4][8];
#pragma unroll
    for (int jj = 0; jj < 4; jj++) {
        const float4* sp = (const float4*)(g_S + ((size_t)b * NN + (c0 + jj)) * KK);
        float4 a = __ldg(sp), b4 = __ldg(sp + 1), c = __ldg(sp + 2), d = __ldg(sp + 3);
        sm[jj][0] = pk2(a.x, a.y);   sm[jj][1] = pk2(a.z, a.w);
        sm[jj][2] = pk2(b4.x, b4.y); sm[jj][3] = pk2(b4.z, b4.w);
        sm[jj][4] = pk2(c.x, c.y);   sm[jj][5] = pk2(c.z, c.w);
        sm[jj][6] = pk2(d.x, d.y);   sm[jj][7] = pk2(d.z, d.w);
    }
    __syncthreads();   // shS tile resident

    const float* Wp = W + ((size_t)b * NN + r0) * NN + c0;

    // Prologue: chunks 0,1,2 into slots 0,1,2 (one commit group each)
#pragma unroll
    for (int k = 0; k < 3; k++) {
        const float* p = Wp + (size_t)k * 4 * NN;
        const uint32_t sb = swbase + (uint32_t)k * slotsz;
#pragma unroll
        for (int i = 0; i < 4; i++)
            cp_async16(sb + (uint32_t)i * plane, p + (size_t)i * NN);
        CP_COMMIT();
    }

    u64p acc0 = 0, acc1 = 0, acc2 = 0, acc3 = 0; // packed num accumulators
    u64p den0 = 0, den1 = 0;                     // packed den accumulators

#pragma unroll 1
    for (int k = 0; k < 64; k++) {               // 64 chunks x 4 rows
        const int slot = k & 3;
        // Issue chunk k+3 (empty commit on the tail keeps group count exact
        // so wait_group 3 always means "chunk k resident").
        if (k + 3 < 64) {
            const float* p = Wp + (size_t)(k + 3) * 4 * NN;
            const uint32_t sb = swbase + (uint32_t)((k + 3) & 3) * slotsz;
#pragma unroll
            for (int i = 0; i < 4; i++)
                cp_async16(sb + (uint32_t)i * plane, p + (size_t)i * NN);
        }
        CP_COMMIT();
        CP_WAIT3();   // chunk k resident

#pragma unroll
        for (int i = 0; i < 4; i++) {
            float4 w = shW[(size_t)slot * 1024 + (size_t)i * 256 + tid];
            const float4* sp = (const float4*)(shS + (size_t)(k * 4 + i) * KK);
            float4 a = sp[0], e = sp[1], c = sp[2], d = sp[3]; // broadcast LDS
            u64p sn0 = pk2(a.x, a.y), sn1 = pk2(a.z, a.w);
            u64p sn2 = pk2(e.x, e.y), sn3 = pk2(e.z, e.w);
            u64p sn4 = pk2(c.x, c.y), sn5 = pk2(c.z, c.w);
            u64p sn6 = pk2(d.x, d.y), sn7 = pk2(d.z, d.w);

            // 4 independent packed dot chains (ILP = 4)
            u64p d0 = mul2(sm[0][0], sn0);
            u64p d1 = mul2(sm[1][0], sn0);
            u64p d2 = mul2(sm[2][0], sn0);
            u64p d3 = mul2(sm[3][0], sn0);
            d0 = fma2(sm[0][1], sn1, d0); d1 = fma2(sm[1][1], sn1, d1);
            d2 = fma2(sm[2][1], sn1, d2); d3 = fma2(sm[3][1], sn1, d3);
            d0 = fma2(sm[0][2], sn2, d0); d1 = fma2(sm[1][2], sn2, d1);
            d2 = fma2(sm[2][2], sn2, d2); d3 = fma2(sm[3][2], sn2, d3);
            d0 = fma2(sm[0][3], sn3, d0); d1 = fma2(sm[1][3], sn3, d1);
            d2 = fma2(sm[2][3], sn3, d2); d3 = fma2(sm[3][3], sn3, d3);
            d0 = fma2(sm[0][4], sn4, d0); d1 = fma2(sm[1][4], sn4, d1);
            d2 = fma2(sm[2][4], sn4, d2); d3 = fma2(sm[3][4], sn4, d3);
            d0 = fma2(sm[0][5], sn5, d0); d1 = fma2(sm[1][5], sn5, d1);
            d2 = fma2(sm[2][5], sn5, d2); d3 = fma2(sm[3][5], sn5, d3);
            d0 = fma2(sm[0][6], sn6, d0); d1 = fma2(sm[1][6], sn6, d1);
            d2 = fma2(sm[2][6], sn6, d2); d3 = fma2(sm[3][6], sn6, d3);
            d0 = fma2(sm[0][7], sn7, d0); d1 = fma2(sm[1][7], sn7, d1);
            d2 = fma2(sm[2][7], sn7, d2); d3 = fma2(sm[3][7], sn7, d3);

            acc0 = fma2(pk2(w.x, w.x), d0, acc0);
            acc1 = fma2(pk2(w.y, w.y), d1, acc1);
            acc2 = fma2(pk2(w.z, w.z), d2, acc2);
            acc3 = fma2(pk2(w.w, w.w), d3, acc3);
            den0 = add2(den0, pk2(w.x, w.y));
            den1 = add2(den1, pk2(w.z, w.w));
        }
    }

    float tnum = (hsum2(acc0) + hsum2(acc1)) + (hsum2(acc2) + hsum2(acc3));
    float tden = hsum2(den0) + hsum2(den1);

    // Block reduction -> one double atomic per block
    __syncthreads();
    rn[tid] = tnum; rd[tid] = tden;
    __syncthreads();
#pragma unroll
    for (int s = 128; s > 0; s >>= 1) {
        if (tid < s) { rn[tid] += rn[tid + s]; rd[tid] += rd[tid + s]; }
        __syncthreads();
    }
    if (tid == 0) {
        atomicAdd(&g_num, (double)rn[0]);
        atomicAdd(&g_den, (double)rd[0]);
    }

    // Fused StS partial: the x==0 blocks cover every row of every batch
    // exactly once; shS is still resident.
    if (blockIdx.x == 0) {
        int k = tid >> 4, j = tid & 15;
        float a0 = 0.f, a1 = 0.f;
#pragma unroll 4
        for (int r = 0; r < 256; r += 2) {
            a0 = fmaf(shS[r * 16 + k],      shS[r * 16 + j],      a0);
            a1 = fmaf(shS[(r + 1) * 16 + k], shS[(r + 1) * 16 + j], a1);
        }
        atomicAdd(&g_StS[b * 256 + tid], (double)(a0 + a1));
    }

    // Fused finalize: last block to finish computes the loss.
    __threadfence();
    __syncthreads();
    __shared__ unsigned s_isLast;
    if (tid == 0)
        s_isLast = (atomicAdd(&g_done, 1u) == W_GRID_BLOCKS - 1) ? 1u : 0u;
    __syncthreads();
    if (s_isLast) {
        int k = tid >> 4, j = tid & 15;
        float s = 0.f;
#pragma unroll
        for (int bi = 0; bi < BB; bi++) {
            float v = (float)__ldcg(&g_StS[bi * 256 + tid]); // L2 (bypass L1)
            float diff = v - (k == j ? 1.0f : 0.0f);
            s += diff * diff;
        }
        rn[tid] = s;
        __syncthreads();
#pragma unroll
        for (int st = 128; st > 0; st >>= 1) {
            if (tid < st) rn[tid] += rn[tid + st];
            __syncthreads();
        }
        if (tid == 0) {
            float ortho = sqrtf(rn[0]) / (float)BB;
            double num = __ldcg(&g_num), den = __ldcg(&g_den);
            out[loss_idx] = -(float)(num / den) + ortho;
            atomicExch(&g_done, 0u);  // reset for next replay
        }
    }
}

// ---------------------------------------------------------------------------
// Launch
// ---------------------------------------------------------------------------
extern "C" void kernel_launch(void* const* d_in, const int* in_sizes, int n_in,
                              void* d_out, int out_size) {
    const float* W = nullptr;
    const float* logits = nullptr;
    for (int i = 0; i < n_in; i++) {
        long sz = (long)in_sizes[i];
        if (sz == (long)BB * NN * NN)      W      = (const float*)d_in[i];
        else if (sz == (long)BB * NN * KK) logits = (const float*)d_in[i];
        // features [B,N,D] is unused by the reference computation
    }
    float* out = (float*)d_out;

    bool want_S    = (out_size >= BNK);
    bool want_loss = (out_size == 1) || (out_size == BNK + 1);

    cudaFuncSetAttribute(w_pass_kernel,
                         cudaFuncAttributeMaxDynamicSharedMemorySize, DYN_SMEM);

    softmax_kernel<<<(BB * NN) / 256, 256>>>(logits, want_S ? out : nullptr);
    if (want_loss) {
        int loss_idx = (out_size == 1) ? 0 : BNK;
        w_pass_kernel<<<dim3(NN / 1024, NN / 256, BB), 256, DYN_SMEM>>>(
            W, out, loss_idx);
    }
}